// round 6
// baseline (speedup 1.0000x reference)
#include <cuda_runtime.h>
#include <cstdint>
#include <math.h>

#define TOKENS 262144      // 4 * 256 * 256
#define CDIM   192
#define QKVN   576
#define NHEADS 6
#define NWINS  4096

__device__ float g_qkv[(size_t)TOKENS * QKVN];
__device__ float g_att[(size_t)TOKENS * CDIM];

__device__ __forceinline__ uint32_t smem_u32(const void* p) {
    uint32_t a;
    asm("{ .reg .u64 t; cvta.to.shared.u64 t, %1; cvt.u32.u64 %0, t; }" : "=r"(a) : "l"(p));
    return a;
}
__device__ __forceinline__ float to_tf32(float x) {
    asm("cvt.rna.tf32.f32 %0, %1;" : "=f"(x) : "f"(x));
    return x;
}
__device__ __forceinline__ uint32_t frag(float x) {   // rna-rounded tf32 bits
    asm("cvt.rna.tf32.f32 %0, %0;" : "+f"(x));
    return __float_as_uint(x);
}
__device__ __forceinline__ void mma_tf32(float* c, const uint32_t* a, const uint32_t* b) {
    asm volatile(
        "mma.sync.aligned.m16n8k8.row.col.f32.tf32.tf32.f32 "
        "{%0,%1,%2,%3}, {%4,%5,%6,%7}, {%8,%9}, {%0,%1,%2,%3};"
        : "+f"(c[0]), "+f"(c[1]), "+f"(c[2]), "+f"(c[3])
        : "r"(a[0]), "r"(a[1]), "r"(a[2]), "r"(a[3]), "r"(b[0]), "r"(b[1]));
}
__device__ __forceinline__ void cpa16(uint32_t dst, const void* src) {
    asm volatile("cp.async.cg.shared.global [%0], [%1], 16;" :: "r"(dst), "l"(src));
}
__device__ __forceinline__ void cpa_commit() {
    asm volatile("cp.async.commit_group;" ::: "memory");
}
template<int N>
__device__ __forceinline__ void cpa_wait() {
    asm volatile("cp.async.wait_group %0;" :: "n"(N) : "memory");
}

// ---------------- warp-mma tf32 GEMM, 3-stage cp.async pipeline ----------------
// C[m][n] = sum_k A[m][k]*W[n][k] + bias[n]
// Block 128x96, 8 warps (4m x 2n), warp tile 32x48, BK=32, K=192 (6 slabs).
template<int NOUT>
__global__ __launch_bounds__(256) void gemm_mma(
    const float* __restrict__ A, const float* __restrict__ W,
    const float* __restrict__ bias, float* __restrict__ C)
{
    extern __shared__ __align__(16) float sm[];
    float* Abuf = sm;                       // 3 * 128*36
    float* Bbuf = sm + 3 * 4608;            // 3 *  96*36
    const uint32_t AbufS = smem_u32(Abuf);
    const uint32_t BbufS = smem_u32(Bbuf);

    const int t    = threadIdx.x;
    const int wid  = t >> 5;
    const int lane = t & 31;
    const int bm   = blockIdx.y * 128;
    const int bn   = blockIdx.x * 96;
    const int m0   = (wid >> 1) * 32;
    const int n0   = (wid & 1) * 48;
    const int gr   = lane >> 2;
    const int gc   = lane & 3;

    float acc[2][6][4];
#pragma unroll
    for (int i = 0; i < 2; ++i)
#pragma unroll
        for (int j = 0; j < 6; ++j)
#pragma unroll
            for (int r = 0; r < 4; ++r) acc[i][j][r] = 0.f;

    auto stage = [&](int slab, int buf) {
        const int k0 = slab * 32;
#pragma unroll
        for (int p = 0; p < 4; ++p) {
            int ci = t + p * 256;
            int r = ci >> 3, c = ci & 7;
            cpa16(AbufS + (uint32_t)(buf * 4608 + r * 36 + c * 4) * 4,
                  A + (size_t)(bm + r) * CDIM + k0 + c * 4);
        }
#pragma unroll
        for (int p = 0; p < 3; ++p) {
            int ci = t + p * 256;
            int r = ci >> 3, c = ci & 7;
            cpa16(BbufS + (uint32_t)(buf * 3456 + r * 36 + c * 4) * 4,
                  W + (size_t)(bn + r) * CDIM + k0 + c * 4);
        }
        cpa_commit();
    };

    stage(0, 0);
    stage(1, 1);

#pragma unroll
    for (int s = 0; s < 6; ++s) {
        if (s < 5) cpa_wait<1>(); else cpa_wait<0>();
        __syncthreads();
        if (s + 2 < 6) stage(s + 2, (s + 2) % 3);   // after sync: safe reuse (dist 3)

        const float* As = Abuf + (s % 3) * 4608;
        const float* Bs = Bbuf + (s % 3) * 3456;
#pragma unroll
        for (int ks4 = 0; ks4 < 4; ++ks4) {
            const int kk = ks4 * 8;
            uint32_t af[2][4], bf[6][2];
#pragma unroll
            for (int mi = 0; mi < 2; ++mi) {
                int rb = m0 + mi * 16 + gr;
                af[mi][0] = frag(As[rb * 36 + kk + gc]);
                af[mi][1] = frag(As[(rb + 8) * 36 + kk + gc]);
                af[mi][2] = frag(As[rb * 36 + kk + gc + 4]);
                af[mi][3] = frag(As[(rb + 8) * 36 + kk + gc + 4]);
            }
#pragma unroll
            for (int ni = 0; ni < 6; ++ni) {
                int nb = n0 + ni * 8 + gr;
                bf[ni][0] = frag(Bs[nb * 36 + kk + gc]);
                bf[ni][1] = frag(Bs[nb * 36 + kk + gc + 4]);
            }
#pragma unroll
            for (int mi = 0; mi < 2; ++mi)
#pragma unroll
                for (int ni = 0; ni < 6; ++ni)
                    mma_tf32(acc[mi][ni], af[mi], bf[ni]);
        }
    }

#pragma unroll
    for (int mi = 0; mi < 2; ++mi) {
        int mr = bm + m0 + mi * 16 + gr;
#pragma unroll
        for (int ni = 0; ni < 6; ++ni) {
            int nc = bn + n0 + ni * 8 + gc * 2;
            float2 bv = __ldg((const float2*)(bias + nc));
            float2 o0 = {acc[mi][ni][0] + bv.x, acc[mi][ni][1] + bv.y};
            float2 o1 = {acc[mi][ni][2] + bv.x, acc[mi][ni][3] + bv.y};
            *(float2*)(C + (size_t)mr * NOUT + nc)       = o0;
            *(float2*)(C + (size_t)(mr + 8) * NOUT + nc) = o1;
        }
    }
}

// ---------------- tensor-core window attention ----------------
// One block (128 thr, 4 warps) per (window, head). Warp w owns S rows [16w,16w+16).
__global__ __launch_bounds__(128) void win_attn(const float* __restrict__ bias)
{
    __shared__ __align__(16) float qs[64][36];   // [tok][d], q*scale (tf32)
    __shared__ __align__(16) float ks_[64][36];  // [tok][d]
    __shared__ __align__(16) float vs[64][40];   // [tok][d], pad 40 -> conflict-free B frags
    __shared__ __align__(16) float ps[64][68];   // softmax probs (64 cols + pad)

    const int pair = blockIdx.x;
    const int head = pair % NHEADS;
    const int win  = pair / NHEADS;
    const int b  = win >> 10;
    const int wy = (win >> 5) & 31;
    const int wx = win & 31;

    const int t    = threadIdx.x;
    const int wid  = t >> 5;
    const int lane = t & 31;
    const int gr   = lane >> 2;
    const int gc   = lane & 3;
    const float scale = 0.17677669529663687f;

    // gather: 64 rows x 8 float4-chunks per stream, 3 streams
#pragma unroll
    for (int i = 0; i < 4; ++i) {
        int idx = t + i * 128;
        int p = idx >> 3;
        int c = idx & 7;
        int h = wy * 8 + (p >> 3);
        int w = wx * 8 + (p & 7);
        const float* base = g_qkv + (size_t)(b * 65536 + h * 256 + w) * QKVN + head * 32 + c * 4;
        float4 qv = *(const float4*)(base);
        float4 kv = *(const float4*)(base + CDIM);
        float4 vv = *(const float4*)(base + 2 * CDIM);
        qs[p][c*4+0] = to_tf32(qv.x * scale); qs[p][c*4+1] = to_tf32(qv.y * scale);
        qs[p][c*4+2] = to_tf32(qv.z * scale); qs[p][c*4+3] = to_tf32(qv.w * scale);
        ks_[p][c*4+0] = to_tf32(kv.x); ks_[p][c*4+1] = to_tf32(kv.y);
        ks_[p][c*4+2] = to_tf32(kv.z); ks_[p][c*4+3] = to_tf32(kv.w);
        vs[p][c*4+0] = to_tf32(vv.x); vs[p][c*4+1] = to_tf32(vv.y);
        vs[p][c*4+2] = to_tf32(vv.z); vs[p][c*4+3] = to_tf32(vv.w);
    }
    __syncthreads();

    // S = q @ k^T  (warp: 16 rows x 64 cols)
    const int m0 = wid * 16;
    float s[8][4];
#pragma unroll
    for (int ni = 0; ni < 8; ++ni)
#pragma unroll
        for (int r = 0; r < 4; ++r) s[ni][r] = 0.f;

#pragma unroll
    for (int ks4 = 0; ks4 < 4; ++ks4) {
        const int kc = ks4 * 8;
        uint32_t a[4];
        a[0] = __float_as_uint(qs[m0 + gr][kc + gc]);
        a[1] = __float_as_uint(qs[m0 + gr + 8][kc + gc]);
        a[2] = __float_as_uint(qs[m0 + gr][kc + gc + 4]);
        a[3] = __float_as_uint(qs[m0 + gr + 8][kc + gc + 4]);
#pragma unroll
        for (int ni = 0; ni < 8; ++ni) {
            uint32_t bfr[2];
            bfr[0] = __float_as_uint(ks_[ni * 8 + gr][kc + gc]);
            bfr[1] = __float_as_uint(ks_[ni * 8 + gr][kc + gc + 4]);
            mma_tf32(s[ni], a, bfr);
        }
    }

    // bias add + register softmax (rows r0 = m0+gr, r1 = r0+8)
    const int r0 = m0 + gr;
    const int r1 = r0 + 8;
    const float* bp = bias + head * 4096;
    float mx0 = -1e30f, mx1 = -1e30f;
#pragma unroll
    for (int ni = 0; ni < 8; ++ni) {
        float2 b0 = __ldg((const float2*)(bp + r0 * 64 + ni * 8 + gc * 2));
        float2 b1 = __ldg((const float2*)(bp + r1 * 64 + ni * 8 + gc * 2));
        s[ni][0] += b0.x; s[ni][1] += b0.y;
        s[ni][2] += b1.x; s[ni][3] += b1.y;
        mx0 = fmaxf(mx0, fmaxf(s[ni][0], s[ni][1]));
        mx1 = fmaxf(mx1, fmaxf(s[ni][2], s[ni][3]));
    }
    mx0 = fmaxf(mx0, __shfl_xor_sync(0xffffffffu, mx0, 1));
    mx0 = fmaxf(mx0, __shfl_xor_sync(0xffffffffu, mx0, 2));
    mx1 = fmaxf(mx1, __shfl_xor_sync(0xffffffffu, mx1, 1));
    mx1 = fmaxf(mx1, __shfl_xor_sync(0xffffffffu, mx1, 2));

    float sum0 = 0.f, sum1 = 0.f;
#pragma unroll
    for (int ni = 0; ni < 8; ++ni) {
        s[ni][0] = __expf(s[ni][0] - mx0);
        s[ni][1] = __expf(s[ni][1] - mx0);
        s[ni][2] = __expf(s[ni][2] - mx1);
        s[ni][3] = __expf(s[ni][3] - mx1);
        sum0 += s[ni][0] + s[ni][1];
        sum1 += s[ni][2] + s[ni][3];
    }
    sum0 += __shfl_xor_sync(0xffffffffu, sum0, 1);
    sum0 += __shfl_xor_sync(0xffffffffu, sum0, 2);
    sum1 += __shfl_xor_sync(0xffffffffu, sum1, 1);
    sum1 += __shfl_xor_sync(0xffffffffu, sum1, 2);
    const float inv0 = 1.f / sum0;
    const float inv1 = 1.f / sum1;

#pragma unroll
    for (int ni = 0; ni < 8; ++ni) {
        ps[r0][ni * 8 + gc * 2]     = to_tf32(s[ni][0] * inv0);
        ps[r0][ni * 8 + gc * 2 + 1] = to_tf32(s[ni][1] * inv0);
        ps[r1][ni * 8 + gc * 2]     = to_tf32(s[ni][2] * inv1);
        ps[r1][ni * 8 + gc * 2 + 1] = to_tf32(s[ni][3] * inv1);
    }
    __syncwarp();

    // O = P @ V  (warp: 16 rows x 32 d);  B[n=d][k=tok] = vs[tok][d]
    float o[4][4];
#pragma unroll
    for (int ni = 0; ni < 4; ++ni)
#pragma unroll
        for (int r = 0; r < 4; ++r) o[ni][r] = 0.f;

#pragma unroll
    for (int ks8 = 0; ks8 < 8; ++ks8) {
        const int kc = ks8 * 8;
        uint32_t a[4];
        a[0] = __float_as_uint(ps[m0 + gr][kc + gc]);
        a[1] = __float_as_uint(ps[m0 + gr + 8][kc + gc]);
        a[2] = __float_as_uint(ps[m0 + gr][kc + gc + 4]);
        a[3] = __float_as_uint(ps[m0 + gr + 8][kc + gc + 4]);
#pragma unroll
        for (int ni = 0; ni < 4; ++ni) {
            uint32_t bfr[2];
            bfr[0] = __float_as_uint(vs[kc + gc][ni * 8 + gr]);
            bfr[1] = __float_as_uint(vs[kc + gc + 4][ni * 8 + gr]);
            mma_tf32(o[ni], a, bfr);
        }
    }

    // scatter O
    {
        int h0 = wy * 8 + (r0 >> 3), w0 = wx * 8 + (r0 & 7);
        int h1 = wy * 8 + (r1 >> 3), w1 = wx * 8 + (r1 & 7);
        size_t tok0 = (size_t)(b * 65536 + h0 * 256 + w0) * CDIM + head * 32;
        size_t tok1 = (size_t)(b * 65536 + h1 * 256 + w1) * CDIM + head * 32;
#pragma unroll
        for (int ni = 0; ni < 4; ++ni) {
            int d = ni * 8 + gc * 2;
            *(float2*)(g_att + tok0 + d) = make_float2(o[ni][0], o[ni][1]);
            *(float2*)(g_att + tok1 + d) = make_float2(o[ni][2], o[ni][3]);
        }
    }
}

extern "C" void kernel_launch(void* const* d_in, const int* in_sizes, int n_in,
                              void* d_out, int out_size)
{
    const float* x      = (const float*)d_in[0];
    const float* qkv_w  = (const float*)d_in[1];
    const float* qkv_b  = (const float*)d_in[2];
    const float* proj_w = (const float*)d_in[3];
    const float* proj_b = (const float*)d_in[4];
    const float* bias   = (const float*)d_in[5];
    float* out = (float*)d_out;

    float *qkv_p = nullptr, *att_p = nullptr;
    cudaGetSymbolAddress((void**)&qkv_p, g_qkv);
    cudaGetSymbolAddress((void**)&att_p, g_att);

    const int smem_bytes = (3 * 4608 + 3 * 3456) * 4;   // 96768
    cudaFuncSetAttribute(gemm_mma<QKVN>, cudaFuncAttributeMaxDynamicSharedMemorySize, smem_bytes);
    cudaFuncSetAttribute(gemm_mma<CDIM>, cudaFuncAttributeMaxDynamicSharedMemorySize, smem_bytes);

    dim3 g1(QKVN / 96, TOKENS / 128);
    gemm_mma<QKVN><<<g1, 256, smem_bytes>>>(x, qkv_w, qkv_b, qkv_p);

    win_attn<<<NWINS * NHEADS, 128>>>(bias);

    dim3 g3(CDIM / 96, TOKENS / 128);
    gemm_mma<CDIM><<<g3, 256, smem_bytes>>>(att_p, proj_w, proj_b, out);
}

// round 8
// speedup vs baseline: 1.0365x; 1.0365x over previous
#include <cuda_runtime.h>
#include <cstdint>
#include <math.h>

#define TOKENS 262144      // 4 * 256 * 256
#define CDIM   192
#define QKVN   576
#define NHEADS 6
#define NWINS  4096

__device__ float g_qkv[(size_t)TOKENS * QKVN];
__device__ float g_att[(size_t)TOKENS * CDIM];
__device__ float g_wq[(size_t)QKVN * CDIM];   // tf32-rounded qkv_w
__device__ float g_wp[(size_t)CDIM * CDIM];   // tf32-rounded proj_w

__device__ __forceinline__ uint32_t smem_u32(const void* p) {
    uint32_t a;
    asm("{ .reg .u64 t; cvta.to.shared.u64 t, %1; cvt.u32.u64 %0, t; }" : "=r"(a) : "l"(p));
    return a;
}
__device__ __forceinline__ float to_tf32(float x) {
    asm("cvt.rna.tf32.f32 %0, %1;" : "=f"(x) : "f"(x));
    return x;
}
__device__ __forceinline__ uint32_t frag_r(float x) {   // rna-rounded tf32 bits
    asm("cvt.rna.tf32.f32 %0, %0;" : "+f"(x));
    return __float_as_uint(x);
}
__device__ __forceinline__ void mma_tf32(float* c, const uint32_t* a, const uint32_t* b) {
    asm volatile(
        "mma.sync.aligned.m16n8k8.row.col.f32.tf32.tf32.f32 "
        "{%0,%1,%2,%3}, {%4,%5,%6,%7}, {%8,%9}, {%0,%1,%2,%3};"
        : "+f"(c[0]), "+f"(c[1]), "+f"(c[2]), "+f"(c[3])
        : "r"(a[0]), "r"(a[1]), "r"(a[2]), "r"(a[3]), "r"(b[0]), "r"(b[1]));
}
__device__ __forceinline__ void cpa16(uint32_t dst, const void* src) {
    asm volatile("cp.async.cg.shared.global [%0], [%1], 16;" :: "r"(dst), "l"(src));
}
__device__ __forceinline__ void cpa_commit() {
    asm volatile("cp.async.commit_group;" ::: "memory");
}
template<int N>
__device__ __forceinline__ void cpa_wait() {
    asm volatile("cp.async.wait_group %0;" :: "n"(N) : "memory");
}

// round weights to tf32 once
__global__ void round_weights(const float* __restrict__ qw, const float* __restrict__ pw)
{
    int i = blockIdx.x * 256 + threadIdx.x;
    if (i < QKVN * CDIM) g_wq[i] = to_tf32(qw[i]);
    if (i < CDIM * CDIM) g_wp[i] = to_tf32(pw[i]);
}

// ---------------- warp-mma tf32 GEMM, 2-stage cp.async pipeline ----------------
// C[m][n] = sum_k A[m][k]*W[n][k] + bias[n]
// Block 128x96, 8 warps (4m x 2n), warp tile 32x48, BK=32, K=192 (6 slabs).
// W must be pre-rounded to tf32. A rounded per-fragment iff ROUND_A.
template<int NOUT, bool ROUND_A>
__global__ __launch_bounds__(256) void gemm_mma(
    const float* __restrict__ A, const float* __restrict__ W,
    const float* __restrict__ bias, float* __restrict__ C)
{
    extern __shared__ __align__(16) float sm[];
    float* Abuf = sm;                       // 2 * 128*36
    float* Bbuf = sm + 2 * 4608;            // 2 *  96*36
    const uint32_t AbufS = smem_u32(Abuf);
    const uint32_t BbufS = smem_u32(Bbuf);

    const int t    = threadIdx.x;
    const int wid  = t >> 5;
    const int lane = t & 31;
    const int bm   = blockIdx.y * 128;
    const int bn   = blockIdx.x * 96;
    const int m0   = (wid >> 1) * 32;
    const int n0   = (wid & 1) * 48;
    const int gr   = lane >> 2;
    const int gc   = lane & 3;

    float acc[2][6][4];
#pragma unroll
    for (int i = 0; i < 2; ++i)
#pragma unroll
        for (int j = 0; j < 6; ++j)
#pragma unroll
            for (int r = 0; r < 4; ++r) acc[i][j][r] = 0.f;

    auto stage = [&](int slab, int buf) {
        const int k0 = slab * 32;
#pragma unroll
        for (int p = 0; p < 4; ++p) {
            int ci = t + p * 256;
            int r = ci >> 3, c = ci & 7;
            cpa16(AbufS + (uint32_t)(buf * 4608 + r * 36 + c * 4) * 4,
                  A + (size_t)(bm + r) * CDIM + k0 + c * 4);
        }
#pragma unroll
        for (int p = 0; p < 3; ++p) {
            int ci = t + p * 256;
            int r = ci >> 3, c = ci & 7;
            cpa16(BbufS + (uint32_t)(buf * 3456 + r * 36 + c * 4) * 4,
                  W + (size_t)(bn + r) * CDIM + k0 + c * 4);
        }
        cpa_commit();
    };

    stage(0, 0);

#pragma unroll
    for (int s = 0; s < 6; ++s) {
        const int buf = s & 1;
        if (s + 1 < 6) stage(s + 1, buf ^ 1);
        if (s + 1 < 6) cpa_wait<1>(); else cpa_wait<0>();
        __syncthreads();

        const float* As = Abuf + buf * 4608;
        const float* Bs = Bbuf + buf * 3456;
#pragma unroll
        for (int ks4 = 0; ks4 < 4; ++ks4) {
            const int kk = ks4 * 8;
            uint32_t af[2][4], bf[6][2];
#pragma unroll
            for (int mi = 0; mi < 2; ++mi) {
                int rb = m0 + mi * 16 + gr;
                if (ROUND_A) {
                    af[mi][0] = frag_r(As[rb * 36 + kk + gc]);
                    af[mi][1] = frag_r(As[(rb + 8) * 36 + kk + gc]);
                    af[mi][2] = frag_r(As[rb * 36 + kk + gc + 4]);
                    af[mi][3] = frag_r(As[(rb + 8) * 36 + kk + gc + 4]);
                } else {
                    af[mi][0] = __float_as_uint(As[rb * 36 + kk + gc]);
                    af[mi][1] = __float_as_uint(As[(rb + 8) * 36 + kk + gc]);
                    af[mi][2] = __float_as_uint(As[rb * 36 + kk + gc + 4]);
                    af[mi][3] = __float_as_uint(As[(rb + 8) * 36 + kk + gc + 4]);
                }
            }
#pragma unroll
            for (int ni = 0; ni < 6; ++ni) {
                int nb = n0 + ni * 8 + gr;
                bf[ni][0] = __float_as_uint(Bs[nb * 36 + kk + gc]);
                bf[ni][1] = __float_as_uint(Bs[nb * 36 + kk + gc + 4]);
            }
#pragma unroll
            for (int mi = 0; mi < 2; ++mi)
#pragma unroll
                for (int ni = 0; ni < 6; ++ni)
                    mma_tf32(acc[mi][ni], af[mi], bf[ni]);
        }
        __syncthreads();
    }

#pragma unroll
    for (int mi = 0; mi < 2; ++mi) {
        int mr = bm + m0 + mi * 16 + gr;
#pragma unroll
        for (int ni = 0; ni < 6; ++ni) {
            int nc = bn + n0 + ni * 8 + gc * 2;
            float2 bv = __ldg((const float2*)(bias + nc));
            float2 o0 = {acc[mi][ni][0] + bv.x, acc[mi][ni][1] + bv.y};
            float2 o1 = {acc[mi][ni][2] + bv.x, acc[mi][ni][3] + bv.y};
            *(float2*)(C + (size_t)mr * NOUT + nc)       = o0;
            *(float2*)(C + (size_t)(mr + 8) * NOUT + nc) = o1;
        }
    }
}

// ---------------- tensor-core window attention ----------------
// One block (128 thr, 4 warps) per (window, head). Warp w owns S rows [16w,16w+16).
// Writes g_att pre-rounded to tf32 (proj GEMM consumes it without CVTs).
__global__ __launch_bounds__(128) void win_attn(const float* __restrict__ bias)
{
    __shared__ __align__(16) float qs[64][36];   // [tok][d], q*scale (tf32)
    __shared__ __align__(16) float ks_[64][36];  // [tok][d]
    __shared__ __align__(16) float vs[64][40];   // [tok][d], pad 40 -> conflict-free B frags
    __shared__ __align__(16) float ps[64][68];   // softmax probs (64 cols + pad)

    const int pair = blockIdx.x;
    const int head = pair % NHEADS;
    const int win  = pair / NHEADS;
    const int b  = win >> 10;
    const int wy = (win >> 5) & 31;
    const int wx = win & 31;

    const int t    = threadIdx.x;
    const int wid  = t >> 5;
    const int lane = t & 31;
    const int gr   = lane >> 2;
    const int gc   = lane & 3;
    const float scale = 0.17677669529663687f;

    // gather: 64 rows x 8 float4-chunks per stream, 3 streams
#pragma unroll
    for (int i = 0; i < 4; ++i) {
        int idx = t + i * 128;
        int p = idx >> 3;
        int c = idx & 7;
        int h = wy * 8 + (p >> 3);
        int w = wx * 8 + (p & 7);
        const float* base = g_qkv + (size_t)(b * 65536 + h * 256 + w) * QKVN + head * 32 + c * 4;
        float4 qv = *(const float4*)(base);
        float4 kv = *(const float4*)(base + CDIM);
        float4 vv = *(const float4*)(base + 2 * CDIM);
        qs[p][c*4+0] = to_tf32(qv.x * scale); qs[p][c*4+1] = to_tf32(qv.y * scale);
        qs[p][c*4+2] = to_tf32(qv.z * scale); qs[p][c*4+3] = to_tf32(qv.w * scale);
        ks_[p][c*4+0] = to_tf32(kv.x); ks_[p][c*4+1] = to_tf32(kv.y);
        ks_[p][c*4+2] = to_tf32(kv.z); ks_[p][c*4+3] = to_tf32(kv.w);
        vs[p][c*4+0] = to_tf32(vv.x); vs[p][c*4+1] = to_tf32(vv.y);
        vs[p][c*4+2] = to_tf32(vv.z); vs[p][c*4+3] = to_tf32(vv.w);
    }
    __syncthreads();

    // S = q @ k^T  (warp: 16 rows x 64 cols)
    const int m0 = wid * 16;
    float s[8][4];
#pragma unroll
    for (int ni = 0; ni < 8; ++ni)
#pragma unroll
        for (int r = 0; r < 4; ++r) s[ni][r] = 0.f;

#pragma unroll
    for (int ks4 = 0; ks4 < 4; ++ks4) {
        const int kc = ks4 * 8;
        uint32_t a[4];
        a[0] = __float_as_uint(qs[m0 + gr][kc + gc]);
        a[1] = __float_as_uint(qs[m0 + gr + 8][kc + gc]);
        a[2] = __float_as_uint(qs[m0 + gr][kc + gc + 4]);
        a[3] = __float_as_uint(qs[m0 + gr + 8][kc + gc + 4]);
#pragma unroll
        for (int ni = 0; ni < 8; ++ni) {
            uint32_t bfr[2];
            bfr[0] = __float_as_uint(ks_[ni * 8 + gr][kc + gc]);
            bfr[1] = __float_as_uint(ks_[ni * 8 + gr][kc + gc + 4]);
            mma_tf32(s[ni], a, bfr);
        }
    }

    // bias add + register softmax (rows r0 = m0+gr, r1 = r0+8)
    const int r0 = m0 + gr;
    const int r1 = r0 + 8;
    const float* bp = bias + head * 4096;
    float mx0 = -1e30f, mx1 = -1e30f;
#pragma unroll
    for (int ni = 0; ni < 8; ++ni) {
        float2 b0 = __ldg((const float2*)(bp + r0 * 64 + ni * 8 + gc * 2));
        float2 b1 = __ldg((const float2*)(bp + r1 * 64 + ni * 8 + gc * 2));
        s[ni][0] += b0.x; s[ni][1] += b0.y;
        s[ni][2] += b1.x; s[ni][3] += b1.y;
        mx0 = fmaxf(mx0, fmaxf(s[ni][0], s[ni][1]));
        mx1 = fmaxf(mx1, fmaxf(s[ni][2], s[ni][3]));
    }
    mx0 = fmaxf(mx0, __shfl_xor_sync(0xffffffffu, mx0, 1));
    mx0 = fmaxf(mx0, __shfl_xor_sync(0xffffffffu, mx0, 2));
    mx1 = fmaxf(mx1, __shfl_xor_sync(0xffffffffu, mx1, 1));
    mx1 = fmaxf(mx1, __shfl_xor_sync(0xffffffffu, mx1, 2));

    float sum0 = 0.f, sum1 = 0.f;
#pragma unroll
    for (int ni = 0; ni < 8; ++ni) {
        s[ni][0] = __expf(s[ni][0] - mx0);
        s[ni][1] = __expf(s[ni][1] - mx0);
        s[ni][2] = __expf(s[ni][2] - mx1);
        s[ni][3] = __expf(s[ni][3] - mx1);
        sum0 += s[ni][0] + s[ni][1];
        sum1 += s[ni][2] + s[ni][3];
    }
    sum0 += __shfl_xor_sync(0xffffffffu, sum0, 1);
    sum0 += __shfl_xor_sync(0xffffffffu, sum0, 2);
    sum1 += __shfl_xor_sync(0xffffffffu, sum1, 1);
    sum1 += __shfl_xor_sync(0xffffffffu, sum1, 2);
    const float inv0 = 1.f / sum0;
    const float inv1 = 1.f / sum1;

#pragma unroll
    for (int ni = 0; ni < 8; ++ni) {
        ps[r0][ni * 8 + gc * 2]     = to_tf32(s[ni][0] * inv0);
        ps[r0][ni * 8 + gc * 2 + 1] = to_tf32(s[ni][1] * inv0);
        ps[r1][ni * 8 + gc * 2]     = to_tf32(s[ni][2] * inv1);
        ps[r1][ni * 8 + gc * 2 + 1] = to_tf32(s[ni][3] * inv1);
    }
    __syncwarp();

    // O = P @ V  (warp: 16 rows x 32 d);  B[n=d][k=tok] = vs[tok][d]
    float o[4][4];
#pragma unroll
    for (int ni = 0; ni < 4; ++ni)
#pragma unroll
        for (int r = 0; r < 4; ++r) o[ni][r] = 0.f;

#pragma unroll
    for (int ks8 = 0; ks8 < 8; ++ks8) {
        const int kc = ks8 * 8;
        uint32_t a[4];
        a[0] = __float_as_uint(ps[m0 + gr][kc + gc]);
        a[1] = __float_as_uint(ps[m0 + gr + 8][kc + gc]);
        a[2] = __float_as_uint(ps[m0 + gr][kc + gc + 4]);
        a[3] = __float_as_uint(ps[m0 + gr + 8][kc + gc + 4]);
#pragma unroll
        for (int ni = 0; ni < 4; ++ni) {
            uint32_t bfr[2];
            bfr[0] = __float_as_uint(vs[kc + gc][ni * 8 + gr]);
            bfr[1] = __float_as_uint(vs[kc + gc + 4][ni * 8 + gr]);
            mma_tf32(o[ni], a, bfr);
        }
    }

    // scatter O (tf32-rounded so proj GEMM needs no A-CVTs)
    {
        int h0 = wy * 8 + (r0 >> 3), w0 = wx * 8 + (r0 & 7);
        int h1 = wy * 8 + (r1 >> 3), w1 = wx * 8 + (r1 & 7);
        size_t tok0 = (size_t)(b * 65536 + h0 * 256 + w0) * CDIM + head * 32;
        size_t tok1 = (size_t)(b * 65536 + h1 * 256 + w1) * CDIM + head * 32;
#pragma unroll
        for (int ni = 0; ni < 4; ++ni) {
            int d = ni * 8 + gc * 2;
            *(float2*)(g_att + tok0 + d) = make_float2(to_tf32(o[ni][0]), to_tf32(o[ni][1]));
            *(float2*)(g_att + tok1 + d) = make_float2(to_tf32(o[ni][2]), to_tf32(o[ni][3]));
        }
    }
}

extern "C" void kernel_launch(void* const* d_in, const int* in_sizes, int n_in,
                              void* d_out, int out_size)
{
    const float* x      = (const float*)d_in[0];
    const float* qkv_w  = (const float*)d_in[1];
    const float* qkv_b  = (const float*)d_in[2];
    const float* proj_w = (const float*)d_in[3];
    const float* proj_b = (const float*)d_in[4];
    const float* bias   = (const float*)d_in[5];
    float* out = (float*)d_out;

    float *qkv_p = nullptr, *att_p = nullptr, *wq_p = nullptr, *wp_p = nullptr;
    cudaGetSymbolAddress((void**)&qkv_p, g_qkv);
    cudaGetSymbolAddress((void**)&att_p, g_att);
    cudaGetSymbolAddress((void**)&wq_p, g_wq);
    cudaGetSymbolAddress((void**)&wp_p, g_wp);

    const int smem_bytes = (2 * 4608 + 2 * 3456) * 4;   // 64512
    cudaFuncSetAttribute(gemm_mma<QKVN, true>,  cudaFuncAttributeMaxDynamicSharedMemorySize, smem_bytes);
    cudaFuncSetAttribute(gemm_mma<CDIM, false>, cudaFuncAttributeMaxDynamicSharedMemorySize, smem_bytes);

    // 0) round weights to tf32 (tiny)
    round_weights<<<(QKVN * CDIM + 255) / 256, 256>>>(qkv_w, proj_w);

    // 1) QKV GEMM: [262144,192] x [576,192]^T + b   (A rounded per-fragment)
    dim3 g1(QKVN / 96, TOKENS / 128);
    gemm_mma<QKVN, true><<<g1, 256, smem_bytes>>>(x, wq_p, qkv_b, qkv_p);

    // 2) Windowed attention (writes tf32-rounded g_att)
    win_attn<<<NWINS * NHEADS, 128>>>(bias);

    // 3) Proj GEMM: [262144,192] x [192,192]^T + b  (both operands pre-rounded)
    dim3 g3(CDIM / 96, TOKENS / 128);
    gemm_mma<CDIM, false><<<g3, 256, smem_bytes>>>(att_p, wp_p, proj_b, out);
}